// round 16
// baseline (speedup 1.0000x reference)
#include <cuda_runtime.h>
#include <cuda_bf16.h>
#include <math.h>
#include <stdint.h>

// Problem constants
#define BB 32
#define TT 1024
#define HH 1024
#define LL 4

// Recurrence config: 64 CTAs x (16 cols, all 32 batches), 8 warps k-split (128 k each)
#define NCTA_R 64
#define CPR    16
// SMEM: Wh hi/lo 64KB + h staging hi/lo 128KB + partials 16KB
#define RNN_SMEM_B (65536 + 131072 + 16384)   // 212992 B

// GEMM smem strides (bank-conflict-free ldmatrix)
#define AS_STRIDE 24
#define WS_STRIDE 136

// -------------------- device scratch --------------------
// Sequence buffers are T-MAJOR: row m = t*BB + b.
__device__ float          g_S [BB * TT * HH];    // fp32 xp buffer (GEMM out, rnn in)
__device__ __nv_bfloat16  g_Ah[BB * TT * HH];    // seq hi (GEMM A operand / rnn out)
__device__ __nv_bfloat16  g_Al[BB * TT * HH];    // seq lo
__device__ __nv_bfloat16  g_Wih[LL * HH * HH];   // Wi hi
__device__ __nv_bfloat16  g_Wil[LL * HH * HH];   // Wi lo
__device__ __nv_bfloat16  g_Whh[LL * HH * HH];   // Wh hi
__device__ __nv_bfloat16  g_Whl[LL * HH * HH];   // Wh lo
__device__ __nv_bfloat16  g_hh[3][BB * HH];      // h hi, triple-buffered ([b][k])
__device__ __nv_bfloat16  g_hl[3][BB * HH];      // h lo, triple-buffered
__device__ unsigned g_prod[8 * 32];              // per-group produce counters (128B apart)
__device__ unsigned g_war;                       // global step-completion counter

// -------------------- helpers --------------------
__device__ __forceinline__ float tanh_acc(float x)
{
    float ax = fabsf(x);
    float e  = __expf(-2.0f * ax);
    float r  = (1.0f - e) / (1.0f + e);
    return copysignf(r, x);
}
__device__ __forceinline__ uint32_t smem_u32(const void* p)
{
    uint32_t a;
    asm("{ .reg .u64 t; cvta.to.shared.u64 t, %1; cvt.u32.u64 %0, t; }" : "=r"(a) : "l"(p));
    return a;
}
__device__ __forceinline__ void cp_async16(uint32_t dst, const void* src)
{
    asm volatile("cp.async.cg.shared.global [%0], [%1], 16;" :: "r"(dst), "l"(src));
}
#define CP_COMMIT() asm volatile("cp.async.commit_group;")
#define CP_WAIT(N)  asm volatile("cp.async.wait_group " #N ";" ::: "memory")

__device__ __forceinline__ void red_release_add(unsigned* p, unsigned v)
{
    asm volatile("red.release.gpu.global.add.u32 [%0], %1;" :: "l"(p), "r"(v) : "memory");
}
__device__ __forceinline__ unsigned ld_acquire(unsigned* p)
{
    unsigned v;
    asm volatile("ld.acquire.gpu.global.u32 %0, [%1];" : "=r"(v) : "l"(p) : "memory");
    return v;
}
__device__ __forceinline__ void poll_ge(unsigned* p, unsigned target)
{
    while (ld_acquire(p) < target) { }
}
__device__ __forceinline__ void ldsm_x4(uint32_t& r0, uint32_t& r1, uint32_t& r2, uint32_t& r3,
                                        uint32_t a)
{
    asm volatile("ldmatrix.sync.aligned.m8n8.x4.shared.b16 {%0,%1,%2,%3}, [%4];"
                 : "=r"(r0), "=r"(r1), "=r"(r2), "=r"(r3) : "r"(a));
}
__device__ __forceinline__ void ldsm_x4_t(uint32_t& r0, uint32_t& r1, uint32_t& r2, uint32_t& r3,
                                          uint32_t a)
{
    asm volatile("ldmatrix.sync.aligned.m8n8.x4.trans.shared.b16 {%0,%1,%2,%3}, [%4];"
                 : "=r"(r0), "=r"(r1), "=r"(r2), "=r"(r3) : "r"(a));
}
__device__ __forceinline__ void mma16816(float* d, uint32_t a0, uint32_t a1, uint32_t a2,
                                         uint32_t a3, uint32_t b0, uint32_t b1)
{
    asm volatile(
        "mma.sync.aligned.m16n8k16.row.col.f32.bf16.bf16.f32 "
        "{%0,%1,%2,%3}, {%4,%5,%6,%7}, {%8,%9}, {%0,%1,%2,%3};"
        : "+f"(d[0]), "+f"(d[1]), "+f"(d[2]), "+f"(d[3])
        : "r"(a0), "r"(a1), "r"(a2), "r"(a3), "r"(b0), "r"(b1));
}

// -------------------- split fp32 -> bf16 hi/lo (elementwise, for weights) ------------
__global__ void __launch_bounds__(256)
split_kernel(const float* __restrict__ src, __nv_bfloat16* __restrict__ hi,
             __nv_bfloat16* __restrict__ lo, int n4)
{
    int i = blockIdx.x * blockDim.x + threadIdx.x;
    const int stride = gridDim.x * blockDim.x;
    const float4* s4 = (const float4*)src;
    __nv_bfloat162* h2 = (__nv_bfloat162*)hi;
    __nv_bfloat162* l2 = (__nv_bfloat162*)lo;
    for (; i < n4; i += stride) {
        float4 v = s4[i];
        __nv_bfloat16 hx = __float2bfloat16(v.x), hy = __float2bfloat16(v.y);
        __nv_bfloat16 hz = __float2bfloat16(v.z), hw = __float2bfloat16(v.w);
        __nv_bfloat162 a; a.x = hx; a.y = hy;
        __nv_bfloat162 b; b.x = hz; b.y = hw;
        __nv_bfloat162 c; c.x = __float2bfloat16(v.x - __bfloat162float(hx));
                          c.y = __float2bfloat16(v.y - __bfloat162float(hy));
        __nv_bfloat162 d; d.x = __float2bfloat16(v.z - __bfloat162float(hz));
                          d.y = __float2bfloat16(v.w - __bfloat162float(hw));
        h2[2 * i] = a; h2[2 * i + 1] = b;
        l2[2 * i] = c; l2[2 * i + 1] = d;
    }
}

// -------------------- split + transpose: x [b][t][h] fp32 -> t-major bf16 hi/lo -----
__global__ void __launch_bounds__(256)
split_tr_kernel(const float* __restrict__ src, __nv_bfloat16* __restrict__ hi,
                __nv_bfloat16* __restrict__ lo)
{
    const int r = blockIdx.x;
    const int b = r >> 10;
    const int t = r & (TT - 1);
    const int dr = t * BB + b;

    const float4* s = (const float4*)(src + (size_t)r * HH) + threadIdx.x;
    __nv_bfloat162* h2 = (__nv_bfloat162*)(hi + (size_t)dr * HH) + threadIdx.x * 2;
    __nv_bfloat162* l2 = (__nv_bfloat162*)(lo + (size_t)dr * HH) + threadIdx.x * 2;

    float4 v = *s;
    __nv_bfloat16 hx = __float2bfloat16(v.x), hy = __float2bfloat16(v.y);
    __nv_bfloat16 hz = __float2bfloat16(v.z), hw = __float2bfloat16(v.w);
    __nv_bfloat162 a; a.x = hx; a.y = hy;
    __nv_bfloat162 bb; bb.x = hz; bb.y = hw;
    __nv_bfloat162 c; c.x = __float2bfloat16(v.x - __bfloat162float(hx));
                      c.y = __float2bfloat16(v.y - __bfloat162float(hy));
    __nv_bfloat162 d; d.x = __float2bfloat16(v.z - __bfloat162float(hz));
                      d.y = __float2bfloat16(v.w - __bfloat162float(hw));
    h2[0] = a; h2[1] = bb;
    l2[0] = c; l2[1] = d;
}

// -------------------- tensor-core GEMM: C = (Ah+Al)@(Wh+Wl) + bias --------------------
__global__ void __launch_bounds__(256, 2)
mma_gemm_kernel(const __nv_bfloat16* __restrict__ Ahg0, const __nv_bfloat16* __restrict__ Alg0,
                const __nv_bfloat16* __restrict__ Whg0, const __nv_bfloat16* __restrict__ Wlg0,
                const float* __restrict__ bias, float* __restrict__ C)
{
    // reset recurrence counters for the following rnn launch (stream order)
    if (blockIdx.x == 0 && blockIdx.y == 0 && threadIdx.x == 0) {
        g_war = 0u;
#pragma unroll
        for (int i = 0; i < 8; i++) g_prod[i * 32] = 0u;
    }

    __shared__ __nv_bfloat16 Ah_s[2][128 * AS_STRIDE];
    __shared__ __nv_bfloat16 Al_s[2][128 * AS_STRIDE];
    __shared__ __nv_bfloat16 Wh_s[2][16 * WS_STRIDE];
    __shared__ __nv_bfloat16 Wl_s[2][16 * WS_STRIDE];

    const int tid  = threadIdx.x;
    const int bn   = blockIdx.x;
    const int bm   = blockIdx.y;
    const int wid  = tid >> 5;
    const int lane = tid & 31;
    const int wr   = wid & 3;
    const int wc   = wid >> 2;

    const int arow  = tid >> 1, ahalf = (tid & 1) * 8;
    const int wrow  = tid >> 4, wseg  = (tid & 15) * 8;

    const __nv_bfloat16* Ahg = Ahg0 + (size_t)(bm * 128 + arow) * HH + ahalf;
    const __nv_bfloat16* Alg = Alg0 + (size_t)(bm * 128 + arow) * HH + ahalf;
    const __nv_bfloat16* Whg = Whg0 + (size_t)wrow * HH + bn * 128 + wseg;
    const __nv_bfloat16* Wlg = Wlg0 + (size_t)wrow * HH + bn * 128 + wseg;

    const uint32_t bAh = smem_u32(Ah_s), bAl = smem_u32(Al_s);
    const uint32_t bWh = smem_u32(Wh_s), bWl = smem_u32(Wl_s);
    const uint32_t dA = (arow * AS_STRIDE + ahalf) * 2;
    const uint32_t dW = (wrow * WS_STRIDE + wseg) * 2;
    const uint32_t ASZ = 128 * AS_STRIDE * 2;
    const uint32_t WSZ = 16 * WS_STRIDE * 2;

    const uint32_t aOff = (((wr * 32) + (lane & 15)) * AS_STRIDE + ((lane >> 4) << 3)) * 2;
    const uint32_t bOff = ((lane & 15) * WS_STRIDE + wc * 64 + ((lane >> 4) << 3)) * 2;

    float acc[2][8][4];
#pragma unroll
    for (int mi = 0; mi < 2; mi++)
#pragma unroll
        for (int ni = 0; ni < 8; ni++)
#pragma unroll
            for (int q = 0; q < 4; q++) acc[mi][ni][q] = 0.0f;

    cp_async16(bAh + dA, Ahg);
    cp_async16(bAl + dA, Alg);
    cp_async16(bWh + dW, Whg);
    cp_async16(bWl + dW, Wlg);
    CP_COMMIT();

    for (int ks = 0; ks < 64; ks++) {
        const uint32_t cur = (ks & 1);
        if (ks < 63) {
            const uint32_t nxt = cur ^ 1;
            const int kb = (ks + 1) * 16;
            cp_async16(bAh + nxt * ASZ + dA, Ahg + kb);
            cp_async16(bAl + nxt * ASZ + dA, Alg + kb);
            cp_async16(bWh + nxt * WSZ + dW, Whg + (size_t)kb * HH);
            cp_async16(bWl + nxt * WSZ + dW, Wlg + (size_t)kb * HH);
            CP_COMMIT();
            CP_WAIT(1);
        } else {
            CP_WAIT(0);
        }
        __syncthreads();

        uint32_t ah[2][4], al[2][4];
#pragma unroll
        for (int mi = 0; mi < 2; mi++) {
            const uint32_t mofs = mi * 16 * AS_STRIDE * 2;
            ldsm_x4(ah[mi][0], ah[mi][1], ah[mi][2], ah[mi][3], bAh + cur * ASZ + aOff + mofs);
            ldsm_x4(al[mi][0], al[mi][1], al[mi][2], al[mi][3], bAl + cur * ASZ + aOff + mofs);
        }
#pragma unroll
        for (int ng = 0; ng < 4; ng++) {
            uint32_t bh[4], blr[4];
            ldsm_x4_t(bh[0], bh[1], bh[2], bh[3], bWh + cur * WSZ + bOff + ng * 32);
            ldsm_x4_t(blr[0], blr[1], blr[2], blr[3], bWl + cur * WSZ + bOff + ng * 32);
#pragma unroll
            for (int mi = 0; mi < 2; mi++) {
                mma16816(acc[mi][2 * ng],     ah[mi][0], ah[mi][1], ah[mi][2], ah[mi][3], bh[0], bh[1]);
                mma16816(acc[mi][2 * ng],     al[mi][0], al[mi][1], al[mi][2], al[mi][3], bh[0], bh[1]);
                mma16816(acc[mi][2 * ng],     ah[mi][0], ah[mi][1], ah[mi][2], ah[mi][3], blr[0], blr[1]);
                mma16816(acc[mi][2 * ng + 1], ah[mi][0], ah[mi][1], ah[mi][2], ah[mi][3], bh[2], bh[3]);
                mma16816(acc[mi][2 * ng + 1], al[mi][0], al[mi][1], al[mi][2], al[mi][3], bh[2], bh[3]);
                mma16816(acc[mi][2 * ng + 1], ah[mi][0], ah[mi][1], ah[mi][2], ah[mi][3], blr[2], blr[3]);
            }
        }
        __syncthreads();
    }

    const int gr  = lane >> 2;
    const int gc2 = (lane & 3) * 2;
#pragma unroll
    for (int mi = 0; mi < 2; mi++) {
        const int row0 = bm * 128 + wr * 32 + mi * 16 + gr;
#pragma unroll
        for (int ni = 0; ni < 8; ni++) {
            const int col = bn * 128 + wc * 64 + ni * 8 + gc2;
            const float b0 = bias[col], b1 = bias[col + 1];
            float2 v0 = { acc[mi][ni][0] + b0, acc[mi][ni][1] + b1 };
            float2 v1 = { acc[mi][ni][2] + b0, acc[mi][ni][3] + b1 };
            *(float2*)(C + (size_t)row0 * HH + col)        = v0;
            *(float2*)(C + (size_t)(row0 + 8) * HH + col)  = v1;
        }
    }
}

// -------------------- Recurrence: producer-consumer signaled, triple-buffered h -------
// CTA c: cols [c*16, c*16+16), all 32 batches. Warp w: k in [w*128, (w+1)*128).
// RAW: warp w polls g_prod[w] >= 8*(t+1)  (producers = CTA group w, 8 CTAs).
// WAR: writing buf[(t+1)%3] needs all CTAs past step t-2: g_war >= 64*(t-1).
// h is written as bf16 hi/lo BOTH to the ring buffers and to oAh/oAl (next layer's
// GEMM operands) -- the inter-layer split kernels are gone.
__global__ void __launch_bounds__(256, 1)
rnn_layer_mma_kernel(const float* __restrict__ xp,
                     const __nv_bfloat16* __restrict__ Whh,
                     const __nv_bfloat16* __restrict__ Whl,
                     __nv_bfloat16* __restrict__ oAh,
                     __nv_bfloat16* __restrict__ oAl)
{
    extern __shared__ char smraw[];
    const uint32_t smb = smem_u32(smraw);
    const uint32_t whb = smb;                 // Wh hi [0,32768), lo [32768,65536)
    const uint32_t hbs = smb + 65536;         // h hi [..+65536), lo next 65536
    float* p_s = (float*)(smraw + 196608);    // 16KB partials

    const int tid  = threadIdx.x;
    const int w    = tid >> 5;
    const int lane = tid & 31;
    const int c0   = blockIdx.x * CPR;
    const int grp  = blockIdx.x >> 3;

    // ---- load Wh slice hi/lo into swizzled SMEM (per layer) ----
    for (int i = tid; i < HH * 2; i += 256) {
        int k = i >> 1, ch = i & 1;
        uint32_t sw = ((uint32_t)(ch ^ ((k >> 2) & 1))) << 4;
        *(uint4*)(smraw + k * 32 + sw) =
            *(const uint4*)(Whh + (size_t)k * HH + c0 + ch * 8);
        *(uint4*)(smraw + 32768 + k * 32 + sw) =
            *(const uint4*)(Whl + (size_t)k * HH + c0 + ch * 8);
    }

    // output mapping: 2 outputs per thread: b = tid>>3, c = (tid&7)*2 (+0,+1)
    const int ob  = tid >> 3;
    const int ocl = (tid & 7) * 2;
    const int oc  = c0 + ocl;

    // ---- h_0 = 0: zero own cols of buffer 0, then signal production ----
    *(uint32_t*)(g_hh[0] + (size_t)ob * HH + oc) = 0u;
    *(uint32_t*)(g_hl[0] + (size_t)ob * HH + oc) = 0u;
    __syncthreads();
    if (tid == 0) red_release_add(&g_prod[grp * 32], 1u);

    const int kbase = w * 128;
    const int kcb   = w * 16;
    const int brow  = lane & 15;
    const int klane = lane >> 4;
    const uint32_t asw   = (uint32_t)(brow & 7);
    const uint32_t bswzB = ((uint32_t)(klane ^ ((brow >> 2) & 1))) << 4;

    int ri = 0;   // read ring index (t % 3)

    for (int t = 0; t < TT; t++) {
        const int wi2 = (ri == 2) ? 0 : ri + 1;
        const __nv_bfloat16* hhc = g_hh[ri];
        const __nv_bfloat16* hlc = g_hl[ri];

        // RAW gate: this warp's k-range producers are done with step t
        poll_ge(&g_prod[w * 32], (unsigned)(8 * (t + 1)));

        // ---- issue copies: 4 groups = (b-half x k-half), each with hi+lo ----
#pragma unroll
        for (int half = 0; half < 2; half++) {
#pragma unroll
            for (int kh = 0; kh < 2; kh++) {
#pragma unroll
                for (int arr = 0; arr < 2; arr++) {
                    const __nv_bfloat16* buf = arr ? hlc : hhc;
                    const uint32_t dbase = hbs + (arr ? 65536u : 0u);
#pragma unroll
                    for (int j = 0; j < 4; j++) {
                        int idx = j * 32 + lane;               // 0..127
                        int b   = half * 16 + (idx >> 3);
                        int ck  = kh * 8 + (idx & 7);
                        uint32_t dst = dbase + (uint32_t)(b * 2048)
                                     + ((((uint32_t)(kcb + ck)) ^ ((uint32_t)(b & 7))) << 4);
                        cp_async16(dst, buf + (size_t)b * HH + kbase + ck * 8);
                    }
                }
                CP_COMMIT();
            }
        }

        // WAR gate (almost always already satisfied; overlaps copy latency)
        if (t >= 2) poll_ge(&g_war, (unsigned)(64 * (t - 1)));

        const size_t xidx = (size_t)(t * BB + ob) * HH + oc;
        const float2 xv = *(const float2*)(xp + xidx);

        float acc[2][2][4];
#pragma unroll
        for (int mi = 0; mi < 2; mi++)
#pragma unroll
            for (int ni = 0; ni < 2; ni++)
#pragma unroll
                for (int q = 0; q < 4; q++) acc[mi][ni][q] = 0.0f;

#define MMA_KS(mi, ks) do {                                                        \
        uint32_t kc = (uint32_t)(kcb + (ks) * 2 + klane);                          \
        uint32_t aaddr = hbs + (uint32_t)((((mi) * 16) + brow) * 2048)             \
                       + ((kc ^ asw) << 4);                                        \
        uint32_t ah0, ah1, ah2, ah3, al0, al1, al2, al3;                           \
        ldsm_x4(ah0, ah1, ah2, ah3, aaddr);                                        \
        ldsm_x4(al0, al1, al2, al3, aaddr + 65536u);                               \
        uint32_t kk = (uint32_t)(kbase + (ks) * 16 + brow);                        \
        uint32_t baddr = whb + kk * 32 + bswzB;                                    \
        uint32_t bh0, bh1, bh2, bh3, bl0, bl1, bl2, bl3;                           \
        ldsm_x4_t(bh0, bh1, bh2, bh3, baddr);                                      \
        ldsm_x4_t(bl0, bl1, bl2, bl3, baddr + 32768u);                             \
        mma16816(acc[mi][0], ah0, ah1, ah2, ah3, bh0, bh1);                        \
        mma16816(acc[mi][0], al0, al1, al2, al3, bh0, bh1);                        \
        mma16816(acc[mi][0], ah0, ah1, ah2, ah3, bl0, bl1);                        \
        mma16816(acc[mi][1], ah0, ah1, ah2, ah3, bh2, bh3);                        \
        mma16816(acc[mi][1], al0, al1, al2, al3, bh2, bh3);                        \
        mma16816(acc[mi][1], ah0, ah1, ah2, ah3, bl2, bl3);                        \
    } while (0)

        CP_WAIT(3); __syncwarp();
        MMA_KS(0, 0); MMA_KS(0, 1); MMA_KS(0, 2); MMA_KS(0, 3);
        CP_WAIT(2); __syncwarp();
        MMA_KS(0, 4); MMA_KS(0, 5); MMA_KS(0, 6); MMA_KS(0, 7);
        CP_WAIT(1); __syncwarp();
        MMA_KS(1, 0); MMA_KS(1, 1); MMA_KS(1, 2); MMA_KS(1, 3);
        CP_WAIT(0); __syncwarp();
        MMA_KS(1, 4); MMA_KS(1, 5); MMA_KS(1, 6); MMA_KS(1, 7);
#undef MMA_KS

        // ---- stash partials p[w][b][c] ----
        const int rr  = lane >> 2;
        const int cc2 = (lane & 3) * 2;
#pragma unroll
        for (int mi = 0; mi < 2; mi++)
#pragma unroll
            for (int ni = 0; ni < 2; ni++) {
                float* pp = p_s + w * 512 + (mi * 16 + rr) * 16 + ni * 8 + cc2;
                *(float2*)pp         = make_float2(acc[mi][ni][0], acc[mi][ni][1]);
                *(float2*)(pp + 128) = make_float2(acc[mi][ni][2], acc[mi][ni][3]);
            }
        __syncthreads();

        // ---- reduce 8 k-partials, tanh, write ----
        float s0 = 0.0f, s1 = 0.0f;
        const float* pr = p_s + ob * 16 + ocl;
#pragma unroll
        for (int j = 0; j < 8; j++) {
            float2 v = *(const float2*)(pr + j * 512);
            s0 += v.x; s1 += v.y;
        }
        const float hn0 = tanh_acc(xv.x + s0);
        const float hn1 = tanh_acc(xv.y + s1);

        __nv_bfloat16 h0h = __float2bfloat16(hn0), h1h = __float2bfloat16(hn1);
        __nv_bfloat162 hh2; hh2.x = h0h; hh2.y = h1h;
        __nv_bfloat162 hl2;
        hl2.x = __float2bfloat16(hn0 - __bfloat162float(h0h));
        hl2.y = __float2bfloat16(hn1 - __bfloat162float(h1h));

        *(__nv_bfloat162*)(g_hh[wi2] + (size_t)ob * HH + oc) = hh2;
        *(__nv_bfloat162*)(g_hl[wi2] + (size_t)ob * HH + oc) = hl2;
        *(__nv_bfloat162*)(oAh + xidx) = hh2;      // fused split: next layer's A operand
        *(__nv_bfloat162*)(oAl + xidx) = hl2;

        __syncthreads();
        if (tid == 0) {
            red_release_add(&g_prod[grp * 32], 1u);   // production of h_{t+1}
            red_release_add(&g_war, 1u);              // step t fully done (reads drained)
        }

        ri = wi2;
    }
}

// -------------------- Final dense head: reads bf16 hi/lo of last timestep -----------
__global__ void __launch_bounds__(256)
fc_kernel(const __nv_bfloat16* __restrict__ Ah, const __nv_bfloat16* __restrict__ Al,
          const float* __restrict__ fcW, const float* __restrict__ fcb,
          float* __restrict__ out)
{
    const int o  = blockIdx.x * 256 + threadIdx.x;
    const int bq = blockIdx.y;
    const size_t roff = (size_t)((TT - 1) * BB + bq) * HH;
    const __nv_bfloat162* H = (const __nv_bfloat162*)(Ah + roff);
    const __nv_bfloat162* L = (const __nv_bfloat162*)(Al + roff);
    float acc = fcb[o];
#pragma unroll 8
    for (int k2 = 0; k2 < HH / 2; k2++) {
        float2 hv = __bfloat1622float2(H[k2]);
        float2 lv = __bfloat1622float2(L[k2]);
        acc = fmaf(hv.x + lv.x, fcW[(size_t)(2 * k2) * HH + o], acc);
        acc = fmaf(hv.y + lv.y, fcW[(size_t)(2 * k2 + 1) * HH + o], acc);
    }
    out[bq * HH + o] = acc;
}

// -------------------- launch --------------------
extern "C" void kernel_launch(void* const* d_in, const int* in_sizes, int n_in,
                              void* d_out, int out_size)
{
    const float* x   = (const float*)d_in[0];
    const float* Wi  = (const float*)d_in[1];
    const float* Wh  = (const float*)d_in[2];
    const float* bl  = (const float*)d_in[3];
    const float* fcW = (const float*)d_in[4];
    const float* fcb = (const float*)d_in[5];
    float* out = (float*)d_out;

    cudaFuncSetAttribute(rnn_layer_mma_kernel,
                         cudaFuncAttributeMaxDynamicSharedMemorySize, RNN_SMEM_B);

    float* S;
    __nv_bfloat16 *Ah, *Al, *Wih, *Wil, *Whh, *Whl;
    cudaGetSymbolAddress((void**)&S,   g_S);
    cudaGetSymbolAddress((void**)&Ah,  g_Ah);
    cudaGetSymbolAddress((void**)&Al,  g_Al);
    cudaGetSymbolAddress((void**)&Wih, g_Wih);
    cudaGetSymbolAddress((void**)&Wil, g_Wil);
    cudaGetSymbolAddress((void**)&Whh, g_Whh);
    cudaGetSymbolAddress((void**)&Whl, g_Whl);

    const dim3 ggrid(8, 256);
    const int NW4 = LL * HH * HH / 4;

    split_tr_kernel<<<BB * TT, 256>>>(x, Ah, Al);
    split_kernel<<<2048, 256>>>(Wi, Wih, Wil, NW4);
    split_kernel<<<2048, 256>>>(Wh, Whh, Whl, NW4);

    for (int l = 0; l < LL; l++) {
        mma_gemm_kernel<<<ggrid, 256>>>(Ah, Al,
                                        Wih + (size_t)l * HH * HH,
                                        Wil + (size_t)l * HH * HH,
                                        bl + l * HH, S);
        rnn_layer_mma_kernel<<<NCTA_R, 256, RNN_SMEM_B>>>(S,
                                        Whh + (size_t)l * HH * HH,
                                        Whl + (size_t)l * HH * HH,
                                        Ah, Al);
    }

    fc_kernel<<<dim3(HH / 256, BB), 256>>>(Ah, Al, fcW, fcb, out);
}